// round 16
// baseline (speedup 1.0000x reference)
#include <cuda_runtime.h>
#include <cuda_bf16.h>
#include <math.h>

#define N_NODES 16384
#define NPG 512
#define B 32
#define E_EDGES 262144
#define H 64
#define HEADS 8
#define DH 8
#define PAD 64
#define LOG2E 1.4426950408889634f

typedef unsigned long long u64;
typedef unsigned int u32;

// ---------------- scratch (device globals; allocation-free) ----------------
__device__ float g_h[N_NODES * H];      // x @ w_gat
__device__ float g_es[N_NODES];         // (h @ att_src) * log2e
__device__ float g_ed[N_NODES];         // (h @ att_dst) * log2e
__device__ float g_x1[N_NODES * H];     // LN1 output
__device__ float g_q[N_NODES * H];
__device__ float g_k[N_NODES * H];
__device__ float g_v[N_NODES * H];
__device__ float g_ao[N_NODES * H];     // attention output (pre-wo)
__device__ int   g_cnt[N_NODES];        // in-degree (atomic cursors)
__device__ int   g_csrc[N_NODES * PAD]; // padded CSR: 64 src slots per dst

__device__ __forceinline__ float leaky02(float e) {
    return e > 0.0f ? e : 0.2f * e;
}

__device__ __forceinline__ float ex2(float x) {
    float r; asm("ex2.approx.f32 %0, %1;" : "=f"(r) : "f"(x)); return r;
}

// ---------------- packed fp32x2 helpers (sm_103a FFMA2) --------------------
__device__ __forceinline__ u64 f2pack(float lo, float hi) {
    u64 r; asm("mov.b64 %0, {%1, %2};" : "=l"(r) : "f"(lo), "f"(hi)); return r;
}
__device__ __forceinline__ void f2unpack(u64 v, float& lo, float& hi) {
    asm("mov.b64 {%0, %1}, %2;" : "=f"(lo), "=f"(hi) : "l"(v));
}
__device__ __forceinline__ u64 fma2(u64 a, u64 b, u64 c) {
    u64 d; asm("fma.rn.f32x2 %0, %1, %2, %3;" : "=l"(d) : "l"(a), "l"(b), "l"(c)); return d;
}
__device__ __forceinline__ u64 add2(u64 a, u64 b) {
    u64 d; asm("add.rn.f32x2 %0, %1, %2;" : "=l"(d) : "l"(a), "l"(b)); return d;
}

// ---------------- single-pass padded CSR scatter ----------------------------
__global__ void kc_scatter_pad(const int* __restrict__ ei) {
    int k = blockIdx.x * blockDim.x + threadIdx.x;   // E/2 threads
    int2 s2 = ((const int2*)ei)[k];
    int2 d2 = ((const int2*)(ei + E_EDGES))[k];
    int p0 = atomicAdd(&g_cnt[d2.x], 1);
    int p1 = atomicAdd(&g_cnt[d2.y], 1);
    if (p0 < PAD) g_csrc[d2.x * PAD + p0] = s2.x;
    if (p1 < PAD) g_csrc[d2.y * PAD + p1] = s2.y;
}

// ---------------- K1: h = x @ w_gat ; es/ed via shfl butterfly -------------
__global__ void k1_gat_proj(const float* __restrict__ x, const float* __restrict__ w,
                            const float* __restrict__ asrc, const float* __restrict__ adst) {
    __shared__ float sw[4096];
    __shared__ float sx[16][64];
    int t = threadIdx.x;                 // 256 threads
    for (int i = t; i < 4096; i += 256) sw[i] = w[i];
    int row0 = blockIdx.x * 16;
    for (int i = t; i < 1024; i += 256) sx[i >> 6][i & 63] = x[row0 * 64 + i];
    __syncthreads();
    int r = t >> 4, j4 = t & 15;
    const float4* sw4 = (const float4*)sw;
    float4 a = make_float4(0.f, 0.f, 0.f, 0.f);
#pragma unroll
    for (int kk = 0; kk < 64; kk++) {
        float xv = sx[r][kk];
        float4 wv = sw4[kk * 16 + j4];
        a.x = fmaf(xv, wv.x, a.x);
        a.y = fmaf(xv, wv.y, a.y);
        a.z = fmaf(xv, wv.z, a.z);
        a.w = fmaf(xv, wv.w, a.w);
    }
    *(float4*)&g_h[(row0 + r) * 64 + j4 * 4] = a;
    float4 av = *(const float4*)&asrc[j4 * 4];
    float4 dv = *(const float4*)&adst[j4 * 4];
    float es = a.x * av.x + a.y * av.y + a.z * av.z + a.w * av.w;
    float ed = a.x * dv.x + a.y * dv.y + a.z * dv.z + a.w * dv.w;
#pragma unroll
    for (int o = 1; o < 16; o <<= 1) {
        es += __shfl_xor_sync(0xffffffffu, es, o);
        ed += __shfl_xor_sync(0xffffffffu, ed, o);
    }
    if (j4 == 0) { g_es[row0 + r] = es * LOG2E; g_ed[row0 + r] = ed * LOG2E; }
}

// ---------------- K5: warp-per-dst GAT agg + ReLU + residual + LN1 ---------
__global__ void k5_gat_agg(const float* __restrict__ x, const float* __restrict__ b_gat,
                           const float* __restrict__ g1, const float* __restrict__ b1) {
    int warp = (blockIdx.x * blockDim.x + threadIdx.x) >> 5;
    int lane = threadIdx.x & 31;
    if (warp >= N_NODES) return;
    int node = warp;
    int deg = g_cnt[node];
    if (deg > PAD) deg = PAD;
    int off = node * PAD;
    float edst = g_ed[node];

    float p_self = ex2(leaky02(g_es[node] + edst));
    float s = p_self;
    float2 hself = *(const float2*)&g_h[node * 64 + lane * 2];
    float accx = p_self * hself.x;
    float accy = p_self * hself.y;

    for (int e0 = 0; e0 < deg; e0 += 32) {
        int e = e0 + lane;
        float p = 0.0f;
        int src = 0;
        if (e < deg) {
            src = g_csrc[off + e];
            p = ex2(leaky02(g_es[src] + edst));
        }
        int cnt = deg - e0; if (cnt > 32) cnt = 32;
        for (int j0 = 0; j0 < cnt; j0 += 8) {
            int bs[8]; float bp[8];
#pragma unroll
            for (int jj = 0; jj < 8; jj++) {
                bs[jj] = __shfl_sync(0xffffffffu, src, j0 + jj);
                bp[jj] = __shfl_sync(0xffffffffu, p, j0 + jj);
            }
            float2 hv[8];
#pragma unroll
            for (int jj = 0; jj < 8; jj++)
                hv[jj] = *(const float2*)&g_h[bs[jj] * 64 + lane * 2];
#pragma unroll
            for (int jj = 0; jj < 8; jj++) {
                accx = fmaf(bp[jj], hv[jj].x, accx);
                accy = fmaf(bp[jj], hv[jj].y, accy);
                s += bp[jj];
            }
        }
    }
    float inv = 1.0f / (s + 1e-16f);
    float2 xv = *(const float2*)&x[node * 64 + lane * 2];
    float2 bg = *(const float2*)&b_gat[lane * 2];
    float v0 = xv.x + fmaxf(accx * inv + bg.x, 0.0f);
    float v1 = xv.y + fmaxf(accy * inv + bg.y, 0.0f);
    float sum = v0 + v1, sumsq = v0 * v0 + v1 * v1;
#pragma unroll
    for (int o = 16; o; o >>= 1) {
        sum   += __shfl_xor_sync(0xffffffffu, sum, o);
        sumsq += __shfl_xor_sync(0xffffffffu, sumsq, o);
    }
    float mu = sum * (1.0f / 64.0f);
    float var = sumsq * (1.0f / 64.0f) - mu * mu;
    float rstd = rsqrtf(var + 1e-5f);
    float2 gv = *(const float2*)&g1[lane * 2];
    float2 bv = *(const float2*)&b1[lane * 2];
    float2 o2;
    o2.x = (v0 - mu) * rstd * gv.x + bv.x;
    o2.y = (v1 - mu) * rstd * gv.y + bv.y;
    *(float2*)&g_x1[node * 64 + lane * 2] = o2;
}

// ---------------- fused QKV projection, 64 rows/block, 4 rows/thread -------
// RT=4 halves the dominant per-row weight LDS traffic vs RT=2.
__global__ void __launch_bounds__(256) k_qkv(
        const float* __restrict__ wq, const float* __restrict__ bq,
        const float* __restrict__ wk, const float* __restrict__ bk,
        const float* __restrict__ wv, const float* __restrict__ bv) {
    __shared__ float swq[4096], swk[4096], swv[4096];
    __shared__ float sx[64][64];
    int t = threadIdx.x;
    for (int i = t; i < 4096; i += 256) { swq[i] = wq[i]; swk[i] = wk[i]; swv[i] = wv[i]; }
    int row0 = blockIdx.x * 64;
    for (int i = t; i < 4096; i += 256) sx[i >> 6][i & 63] = g_x1[row0 * 64 + i];
    __syncthreads();
    int rp = t >> 4, j4 = t & 15;     // rows 4rp..4rp+3
    const float4* wq4 = (const float4*)swq;
    const float4* wk4 = (const float4*)swk;
    const float4* wv4 = (const float4*)swv;
    u64 qa[4][2] = {}, ka[4][2] = {}, va[4][2] = {};
#pragma unroll 4
    for (int kk = 0; kk < 64; kk++) {
        u64 xx[4];
#pragma unroll
        for (int r = 0; r < 4; r++) {
            float xv = sx[4 * rp + r][kk];
            xx[r] = f2pack(xv, xv);
        }
        float4 q = wq4[kk * 16 + j4];
        u64 qlo = f2pack(q.x, q.y), qhi = f2pack(q.z, q.w);
#pragma unroll
        for (int r = 0; r < 4; r++) {
            qa[r][0] = fma2(xx[r], qlo, qa[r][0]);
            qa[r][1] = fma2(xx[r], qhi, qa[r][1]);
        }
        float4 k = wk4[kk * 16 + j4];
        u64 klo = f2pack(k.x, k.y), khi = f2pack(k.z, k.w);
#pragma unroll
        for (int r = 0; r < 4; r++) {
            ka[r][0] = fma2(xx[r], klo, ka[r][0]);
            ka[r][1] = fma2(xx[r], khi, ka[r][1]);
        }
        float4 v = wv4[kk * 16 + j4];
        u64 vlo = f2pack(v.x, v.y), vhi = f2pack(v.z, v.w);
#pragma unroll
        for (int r = 0; r < 4; r++) {
            va[r][0] = fma2(xx[r], vlo, va[r][0]);
            va[r][1] = fma2(xx[r], vhi, va[r][1]);
        }
    }
    float4 bqv = *(const float4*)&bq[j4 * 4];
    float4 bkv = *(const float4*)&bk[j4 * 4];
    float4 bvv = *(const float4*)&bv[j4 * 4];
    float a, b, c, d;
#pragma unroll
    for (int r = 0; r < 4; r++) {
        int o = (row0 + 4 * rp + r) * 64 + j4 * 4;
        f2unpack(qa[r][0], a, b); f2unpack(qa[r][1], c, d);
        *(float4*)&g_q[o] = make_float4(a + bqv.x, b + bqv.y, c + bqv.z, d + bqv.w);
        f2unpack(ka[r][0], a, b); f2unpack(ka[r][1], c, d);
        *(float4*)&g_k[o] = make_float4(a + bkv.x, b + bkv.y, c + bkv.z, d + bkv.w);
        f2unpack(va[r][0], a, b); f2unpack(va[r][1], c, d);
        *(float4*)&g_v[o] = make_float4(a + bvv.x, b + bvv.y, c + bvv.z, d + bvv.w);
    }
}

// ---------------- K6: dense attention, max-free softmax, QT=4 --------------
// grid = B*HEADS (256 blocks), 128 threads; each thread owns 4 queries.
__global__ void __launch_bounds__(128) k6_attn() {
    __shared__ float sK[8][512];        // d-major, float4 = 4 keys per LDS.128
    __shared__ float4 sV4[512][2];      // key-major 32B rows
    int bh = blockIdx.x;
    int b = bh >> 3, h = bh & 7;
    int base = b * NPG;
    int tid = threadIdx.x;
    for (int i = tid; i < 1024; i += 128) {
        int n = i >> 1, pp = i & 1;
        float4 kv = *(const float4*)&g_k[(base + n) * 64 + h * DH + pp * 4];
        sK[pp * 4 + 0][n] = kv.x;
        sK[pp * 4 + 1][n] = kv.y;
        sK[pp * 4 + 2][n] = kv.z;
        sK[pp * 4 + 3][n] = kv.w;
        sV4[n][pp] = *(const float4*)&g_v[(base + n) * 64 + h * DH + pp * 4];
    }
    __syncthreads();

    const float scale = 0.3535533905932738f * LOG2E;   // log2e/sqrt(8)
    u64 qq[4][8];
#pragma unroll
    for (int qi = 0; qi < 4; qi++) {
        const float* p = &g_q[(base + tid + qi * 128) * 64 + h * DH];
#pragma unroll
        for (int d = 0; d < 8; d++) {
            float a = p[d] * scale;
            qq[qi][d] = f2pack(a, a);
        }
    }

    u64 sum[4] = {0ULL, 0ULL, 0ULL, 0ULL};
    u64 acc[4][4] = {};

#pragma unroll 1
    for (int k0 = 0; k0 < NPG; k0 += 4) {
        u64 sA[4] = {0ULL, 0ULL, 0ULL, 0ULL};
        u64 sB[4] = {0ULL, 0ULL, 0ULL, 0ULL};
#pragma unroll
        for (int d = 0; d < 8; d++) {
            float4 kv = *(const float4*)&sK[d][k0];
            u64 k01 = f2pack(kv.x, kv.y);
            u64 k23 = f2pack(kv.z, kv.w);
#pragma unroll
            for (int qi = 0; qi < 4; qi++) {
                sA[qi] = fma2(qq[qi][d], k01, sA[qi]);
                sB[qi] = fma2(qq[qi][d], k23, sB[qi]);
            }
        }
        float p[4][4];
#pragma unroll
        for (int qi = 0; qi < 4; qi++) {
            float s0, s1;
            f2unpack(sA[qi], s0, s1); p[qi][0] = ex2(s0); p[qi][1] = ex2(s1);
            f2unpack(sB[qi], s0, s1); p[qi][2] = ex2(s0); p[qi][3] = ex2(s1);
            sum[qi] = add2(sum[qi], f2pack(p[qi][0], p[qi][1]));
            sum[qi] = add2(sum[qi], f2pack(p[qi][2], p[qi][3]));
        }
#pragma unroll
        for (int j = 0; j < 4; j++) {
            float4 vlo = sV4[k0 + j][0];
            float4 vhi = sV4[k0 + j][1];
            u64 v0 = f2pack(vlo.x, vlo.y);
            u64 v1 = f2pack(vlo.z, vlo.w);
            u64 v2 = f2pack(vhi.x, vhi.y);
            u64 v3 = f2pack(vhi.z, vhi.w);
#pragma unroll
            for (int qi = 0; qi < 4; qi++) {
                u64 pp = f2pack(p[qi][j], p[qi][j]);
                acc[qi][0] = fma2(pp, v0, acc[qi][0]);
                acc[qi][1] = fma2(pp, v1, acc[qi][1]);
                acc[qi][2] = fma2(pp, v2, acc[qi][2]);
                acc[qi][3] = fma2(pp, v3, acc[qi][3]);
            }
        }
    }
#pragma unroll
    for (int qi = 0; qi < 4; qi++) {
        float sl, sh; f2unpack(sum[qi], sl, sh);
        float inv = 1.0f / (sl + sh);
        float o[8];
#pragma unroll
        for (int pp = 0; pp < 4; pp++) f2unpack(acc[qi][pp], o[2 * pp], o[2 * pp + 1]);
        float* op = &g_ao[(base + tid + qi * 128) * 64 + h * DH];
        *(float4*)&op[0] = make_float4(o[0] * inv, o[1] * inv, o[2] * inv, o[3] * inv);
        *(float4*)&op[4] = make_float4(o[4] * inv, o[5] * inv, o[6] * inv, o[7] * inv);
    }
}

// ---------------- K7: out = LN(x1 + relu(ao @ wo + bo)) --------------------
__global__ void k7_out(const float* __restrict__ wo, const float* __restrict__ bo,
                       const float* __restrict__ g2, const float* __restrict__ b2,
                       float* __restrict__ out) {
    __shared__ float sw[4096];
    __shared__ float sx[16][64];
    int t = threadIdx.x;
    for (int i = t; i < 4096; i += 256) sw[i] = wo[i];
    int row0 = blockIdx.x * 16;
    for (int i = t; i < 1024; i += 256) sx[i >> 6][i & 63] = g_ao[row0 * 64 + i];
    __syncthreads();
    int r = t >> 4, j4 = t & 15;
    const float4* sw4 = (const float4*)sw;
    float4 a = make_float4(0.f, 0.f, 0.f, 0.f);
#pragma unroll
    for (int kk = 0; kk < 64; kk++) {
        float xv = sx[r][kk];
        float4 wv = sw4[kk * 16 + j4];
        a.x = fmaf(xv, wv.x, a.x);
        a.y = fmaf(xv, wv.y, a.y);
        a.z = fmaf(xv, wv.z, a.z);
        a.w = fmaf(xv, wv.w, a.w);
    }
    float4 bv = *(const float4*)&bo[j4 * 4];
    a.x = fmaxf(a.x + bv.x, 0.0f);
    a.y = fmaxf(a.y + bv.y, 0.0f);
    a.z = fmaxf(a.z + bv.z, 0.0f);
    a.w = fmaxf(a.w + bv.w, 0.0f);
    float4 x1v = *(const float4*)&g_x1[(row0 + r) * 64 + j4 * 4];
    float4 val = make_float4(x1v.x + a.x, x1v.y + a.y, x1v.z + a.z, x1v.w + a.w);
    float vsum = val.x + val.y + val.z + val.w;
    float vsq  = val.x * val.x + val.y * val.y + val.z * val.z + val.w * val.w;
#pragma unroll
    for (int o = 1; o < 16; o <<= 1) {
        vsum += __shfl_xor_sync(0xffffffffu, vsum, o);
        vsq  += __shfl_xor_sync(0xffffffffu, vsq, o);
    }
    float mu = vsum * (1.0f / 64.0f);
    float var = vsq * (1.0f / 64.0f) - mu * mu;
    float rstd = rsqrtf(var + 1e-5f);
    float4 gv = *(const float4*)&g2[j4 * 4];
    float4 bb = *(const float4*)&b2[j4 * 4];
    float4 ov;
    ov.x = (val.x - mu) * rstd * gv.x + bb.x;
    ov.y = (val.y - mu) * rstd * gv.y + bb.y;
    ov.z = (val.z - mu) * rstd * gv.z + bb.z;
    ov.w = (val.w - mu) * rstd * gv.w + bb.w;
    *(float4*)&out[(row0 + r) * 64 + j4 * 4] = ov;
}

// ---------------- launch ----------------------------------------------------
extern "C" void kernel_launch(void* const* d_in, const int* in_sizes, int n_in,
                              void* d_out, int out_size) {
    const float* x       = (const float*)d_in[0];
    const float* w_gat   = (const float*)d_in[1];
    const float* att_src = (const float*)d_in[2];
    const float* att_dst = (const float*)d_in[3];
    const float* b_gat   = (const float*)d_in[4];
    const float* g1      = (const float*)d_in[5];
    const float* b1      = (const float*)d_in[6];
    const float* wq      = (const float*)d_in[7];
    const float* bq      = (const float*)d_in[8];
    const float* wk      = (const float*)d_in[9];
    const float* bk      = (const float*)d_in[10];
    const float* wv      = (const float*)d_in[11];
    const float* bv      = (const float*)d_in[12];
    const float* wo      = (const float*)d_in[13];
    const float* bo      = (const float*)d_in[14];
    const float* g2      = (const float*)d_in[15];
    const float* b2      = (const float*)d_in[16];
    const int*   ei      = (const int*)d_in[17];
    float* out = (float*)d_out;

    static cudaStream_t s2 = nullptr;
    static cudaEvent_t evFork = nullptr, evJoin = nullptr;
    static void* cnt_addr = nullptr;
    if (s2 == nullptr) {
        cudaStreamCreateWithFlags(&s2, cudaStreamNonBlocking);
        cudaEventCreateWithFlags(&evFork, cudaEventDisableTiming);
        cudaEventCreateWithFlags(&evJoin, cudaEventDisableTiming);
        cudaGetSymbolAddress(&cnt_addr, g_cnt);
    }

    // fork: k1 (depends only on inputs) runs concurrently with CSR build
    cudaEventRecord(evFork, 0);
    cudaStreamWaitEvent(s2, evFork, 0);
    k1_gat_proj<<<N_NODES / 16, 256, 0, s2>>>(x, w_gat, att_src, att_dst);
    cudaEventRecord(evJoin, s2);

    cudaMemsetAsync(cnt_addr, 0, N_NODES * sizeof(int), 0);
    kc_scatter_pad<<<E_EDGES / 2 / 256, 256>>>(ei);

    // join: k5 needs both k1 outputs and CSR
    cudaStreamWaitEvent(0, evJoin, 0);
    k5_gat_agg<<<N_NODES * 32 / 256, 256>>>(x, b_gat, g1, b1);
    k_qkv<<<N_NODES / 64, 256>>>(wq, bq, wk, bk, wv, bv);
    k6_attn<<<B * HEADS, 128>>>();
    k7_out<<<N_NODES / 16, 256>>>(wo, bo, g2, b2, out);
}

// round 17
// speedup vs baseline: 1.0153x; 1.0153x over previous
#include <cuda_runtime.h>
#include <cuda_bf16.h>
#include <math.h>

#define N_NODES 16384
#define NPG 512
#define B 32
#define E_EDGES 262144
#define H 64
#define HEADS 8
#define DH 8
#define PAD 64
#define LOG2E 1.4426950408889634f

typedef unsigned long long u64;
typedef unsigned int u32;

// ---------------- scratch (device globals; allocation-free) ----------------
__device__ float g_h[N_NODES * H];      // x @ w_gat
__device__ float g_es[N_NODES];         // (h @ att_src) * log2e
__device__ float g_ed[N_NODES];         // (h @ att_dst) * log2e
__device__ float g_x1[N_NODES * H];     // LN1 output
__device__ float g_q[N_NODES * H];
__device__ float g_k[N_NODES * H];
__device__ float g_v[N_NODES * H];
__device__ float g_ao[N_NODES * H];     // attention output (pre-wo)
__device__ int   g_cnt[N_NODES];        // in-degree (atomic cursors)
__device__ int   g_csrc[N_NODES * PAD]; // padded CSR: 64 src slots per dst

__device__ __forceinline__ float leaky02(float e) {
    return e > 0.0f ? e : 0.2f * e;
}

__device__ __forceinline__ float ex2(float x) {
    float r; asm("ex2.approx.f32 %0, %1;" : "=f"(r) : "f"(x)); return r;
}

// ---------------- packed fp32x2 helpers (sm_103a FFMA2) --------------------
__device__ __forceinline__ u64 f2pack(float lo, float hi) {
    u64 r; asm("mov.b64 %0, {%1, %2};" : "=l"(r) : "f"(lo), "f"(hi)); return r;
}
__device__ __forceinline__ void f2unpack(u64 v, float& lo, float& hi) {
    asm("mov.b64 {%0, %1}, %2;" : "=f"(lo), "=f"(hi) : "l"(v));
}
__device__ __forceinline__ u64 fma2(u64 a, u64 b, u64 c) {
    u64 d; asm("fma.rn.f32x2 %0, %1, %2, %3;" : "=l"(d) : "l"(a), "l"(b), "l"(c)); return d;
}
__device__ __forceinline__ u64 add2(u64 a, u64 b) {
    u64 d; asm("add.rn.f32x2 %0, %1, %2;" : "=l"(d) : "l"(a), "l"(b)); return d;
}

// ---------------- single-pass padded CSR scatter ----------------------------
__global__ void kc_scatter_pad(const int* __restrict__ ei) {
    int k = blockIdx.x * blockDim.x + threadIdx.x;   // E/2 threads
    int2 s2 = ((const int2*)ei)[k];
    int2 d2 = ((const int2*)(ei + E_EDGES))[k];
    int p0 = atomicAdd(&g_cnt[d2.x], 1);
    int p1 = atomicAdd(&g_cnt[d2.y], 1);
    if (p0 < PAD) g_csrc[d2.x * PAD + p0] = s2.x;
    if (p1 < PAD) g_csrc[d2.y * PAD + p1] = s2.y;
}

// ---------------- K1: h = x @ w_gat ; es/ed via shfl butterfly -------------
__global__ void k1_gat_proj(const float* __restrict__ x, const float* __restrict__ w,
                            const float* __restrict__ asrc, const float* __restrict__ adst) {
    __shared__ float sw[4096];
    __shared__ float sx[16][64];
    int t = threadIdx.x;                 // 256 threads
    for (int i = t; i < 4096; i += 256) sw[i] = w[i];
    int row0 = blockIdx.x * 16;
    for (int i = t; i < 1024; i += 256) sx[i >> 6][i & 63] = x[row0 * 64 + i];
    __syncthreads();
    int r = t >> 4, j4 = t & 15;
    const float4* sw4 = (const float4*)sw;
    float4 a = make_float4(0.f, 0.f, 0.f, 0.f);
#pragma unroll
    for (int kk = 0; kk < 64; kk++) {
        float xv = sx[r][kk];
        float4 wv = sw4[kk * 16 + j4];
        a.x = fmaf(xv, wv.x, a.x);
        a.y = fmaf(xv, wv.y, a.y);
        a.z = fmaf(xv, wv.z, a.z);
        a.w = fmaf(xv, wv.w, a.w);
    }
    *(float4*)&g_h[(row0 + r) * 64 + j4 * 4] = a;
    float4 av = *(const float4*)&asrc[j4 * 4];
    float4 dv = *(const float4*)&adst[j4 * 4];
    float es = a.x * av.x + a.y * av.y + a.z * av.z + a.w * av.w;
    float ed = a.x * dv.x + a.y * dv.y + a.z * dv.z + a.w * dv.w;
#pragma unroll
    for (int o = 1; o < 16; o <<= 1) {
        es += __shfl_xor_sync(0xffffffffu, es, o);
        ed += __shfl_xor_sync(0xffffffffu, ed, o);
    }
    if (j4 == 0) { g_es[row0 + r] = es * LOG2E; g_ed[row0 + r] = ed * LOG2E; }
}

// ---------------- K5: warp-per-dst GAT agg + ReLU + residual + LN1 ---------
__global__ void k5_gat_agg(const float* __restrict__ x, const float* __restrict__ b_gat,
                           const float* __restrict__ g1, const float* __restrict__ b1) {
    int warp = (blockIdx.x * blockDim.x + threadIdx.x) >> 5;
    int lane = threadIdx.x & 31;
    if (warp >= N_NODES) return;
    int node = warp;
    int deg = g_cnt[node];
    if (deg > PAD) deg = PAD;
    int off = node * PAD;
    float edst = g_ed[node];

    float p_self = ex2(leaky02(g_es[node] + edst));
    float s = p_self;
    float2 hself = *(const float2*)&g_h[node * 64 + lane * 2];
    float accx = p_self * hself.x;
    float accy = p_self * hself.y;

    for (int e0 = 0; e0 < deg; e0 += 32) {
        int e = e0 + lane;
        float p = 0.0f;
        int src = 0;
        if (e < deg) {
            src = g_csrc[off + e];
            p = ex2(leaky02(g_es[src] + edst));
        }
        int cnt = deg - e0; if (cnt > 32) cnt = 32;
        for (int j0 = 0; j0 < cnt; j0 += 8) {
            int bs[8]; float bp[8];
#pragma unroll
            for (int jj = 0; jj < 8; jj++) {
                bs[jj] = __shfl_sync(0xffffffffu, src, j0 + jj);
                bp[jj] = __shfl_sync(0xffffffffu, p, j0 + jj);
            }
            float2 hv[8];
#pragma unroll
            for (int jj = 0; jj < 8; jj++)
                hv[jj] = *(const float2*)&g_h[bs[jj] * 64 + lane * 2];
#pragma unroll
            for (int jj = 0; jj < 8; jj++) {
                accx = fmaf(bp[jj], hv[jj].x, accx);
                accy = fmaf(bp[jj], hv[jj].y, accy);
                s += bp[jj];
            }
        }
    }
    float inv = 1.0f / (s + 1e-16f);
    float2 xv = *(const float2*)&x[node * 64 + lane * 2];
    float2 bg = *(const float2*)&b_gat[lane * 2];
    float v0 = xv.x + fmaxf(accx * inv + bg.x, 0.0f);
    float v1 = xv.y + fmaxf(accy * inv + bg.y, 0.0f);
    float sum = v0 + v1, sumsq = v0 * v0 + v1 * v1;
#pragma unroll
    for (int o = 16; o; o >>= 1) {
        sum   += __shfl_xor_sync(0xffffffffu, sum, o);
        sumsq += __shfl_xor_sync(0xffffffffu, sumsq, o);
    }
    float mu = sum * (1.0f / 64.0f);
    float var = sumsq * (1.0f / 64.0f) - mu * mu;
    float rstd = rsqrtf(var + 1e-5f);
    float2 gv = *(const float2*)&g1[lane * 2];
    float2 bv = *(const float2*)&b1[lane * 2];
    float2 o2;
    o2.x = (v0 - mu) * rstd * gv.x + bv.x;
    o2.y = (v1 - mu) * rstd * gv.y + bv.y;
    *(float2*)&g_x1[node * 64 + lane * 2] = o2;
}

// ---------------- fused QKV projection: 512 thr, 64 rows/block, RT=2 -------
// Same per-thread loop as the proven RT=2 version, but 512-thread blocks:
// ~58 regs -> 2 blocks/SM by registers = 32 warps/SM (vs ~13), hiding the
// LDS latency that kept issue at 21%.
__global__ void __launch_bounds__(512) k_qkv(
        const float* __restrict__ wq, const float* __restrict__ bq,
        const float* __restrict__ wk, const float* __restrict__ bk,
        const float* __restrict__ wv, const float* __restrict__ bv) {
    __shared__ float swq[4096], swk[4096], swv[4096];
    __shared__ float sx[64][64];
    int t = threadIdx.x;
    for (int i = t; i < 4096; i += 512) { swq[i] = wq[i]; swk[i] = wk[i]; swv[i] = wv[i]; }
    int row0 = blockIdx.x * 64;
    for (int i = t; i < 4096; i += 512) sx[i >> 6][i & 63] = g_x1[row0 * 64 + i];
    __syncthreads();
    int rp = t >> 4, j4 = t & 15;     // rows 2rp, 2rp+1 (rp in 0..31)
    const float4* wq4 = (const float4*)swq;
    const float4* wk4 = (const float4*)swk;
    const float4* wv4 = (const float4*)swv;
    u64 q0lo = 0, q0hi = 0, q1lo = 0, q1hi = 0;
    u64 k0lo = 0, k0hi = 0, k1lo = 0, k1hi = 0;
    u64 v0lo = 0, v0hi = 0, v1lo = 0, v1hi = 0;
#pragma unroll 8
    for (int kk = 0; kk < 64; kk++) {
        float x0 = sx[2 * rp][kk], x1 = sx[2 * rp + 1][kk];
        u64 xx0 = f2pack(x0, x0), xx1 = f2pack(x1, x1);
        float4 q = wq4[kk * 16 + j4];
        u64 qlo = f2pack(q.x, q.y), qhi = f2pack(q.z, q.w);
        q0lo = fma2(xx0, qlo, q0lo); q0hi = fma2(xx0, qhi, q0hi);
        q1lo = fma2(xx1, qlo, q1lo); q1hi = fma2(xx1, qhi, q1hi);
        float4 k = wk4[kk * 16 + j4];
        u64 klo = f2pack(k.x, k.y), khi = f2pack(k.z, k.w);
        k0lo = fma2(xx0, klo, k0lo); k0hi = fma2(xx0, khi, k0hi);
        k1lo = fma2(xx1, klo, k1lo); k1hi = fma2(xx1, khi, k1hi);
        float4 v = wv4[kk * 16 + j4];
        u64 vlo = f2pack(v.x, v.y), vhi = f2pack(v.z, v.w);
        v0lo = fma2(xx0, vlo, v0lo); v0hi = fma2(xx0, vhi, v0hi);
        v1lo = fma2(xx1, vlo, v1lo); v1hi = fma2(xx1, vhi, v1hi);
    }
    float4 bqv = *(const float4*)&bq[j4 * 4];
    float4 bkv = *(const float4*)&bk[j4 * 4];
    float4 bvv = *(const float4*)&bv[j4 * 4];
    int o0 = (row0 + 2 * rp) * 64 + j4 * 4;
    int o1 = o0 + 64;
    float a, b, c, d;
    f2unpack(q0lo, a, b); f2unpack(q0hi, c, d);
    *(float4*)&g_q[o0] = make_float4(a + bqv.x, b + bqv.y, c + bqv.z, d + bqv.w);
    f2unpack(q1lo, a, b); f2unpack(q1hi, c, d);
    *(float4*)&g_q[o1] = make_float4(a + bqv.x, b + bqv.y, c + bqv.z, d + bqv.w);
    f2unpack(k0lo, a, b); f2unpack(k0hi, c, d);
    *(float4*)&g_k[o0] = make_float4(a + bkv.x, b + bkv.y, c + bkv.z, d + bkv.w);
    f2unpack(k1lo, a, b); f2unpack(k1hi, c, d);
    *(float4*)&g_k[o1] = make_float4(a + bkv.x, b + bkv.y, c + bkv.z, d + bkv.w);
    f2unpack(v0lo, a, b); f2unpack(v0hi, c, d);
    *(float4*)&g_v[o0] = make_float4(a + bvv.x, b + bvv.y, c + bvv.z, d + bvv.w);
    f2unpack(v1lo, a, b); f2unpack(v1hi, c, d);
    *(float4*)&g_v[o1] = make_float4(a + bvv.x, b + bvv.y, c + bvv.z, d + bvv.w);
}

// ---------------- K6: dense attention, max-free softmax, QT=4 --------------
// grid = B*HEADS (256 blocks), 128 threads; each thread owns 4 queries.
__global__ void __launch_bounds__(128) k6_attn() {
    __shared__ float sK[8][512];        // d-major, float4 = 4 keys per LDS.128
    __shared__ float4 sV4[512][2];      // key-major 32B rows
    int bh = blockIdx.x;
    int b = bh >> 3, h = bh & 7;
    int base = b * NPG;
    int tid = threadIdx.x;
    for (int i = tid; i < 1024; i += 128) {
        int n = i >> 1, pp = i & 1;
        float4 kv = *(const float4*)&g_k[(base + n) * 64 + h * DH + pp * 4];
        sK[pp * 4 + 0][n] = kv.x;
        sK[pp * 4 + 1][n] = kv.y;
        sK[pp * 4 + 2][n] = kv.z;
        sK[pp * 4 + 3][n] = kv.w;
        sV4[n][pp] = *(const float4*)&g_v[(base + n) * 64 + h * DH + pp * 4];
    }
    __syncthreads();

    const float scale = 0.3535533905932738f * LOG2E;   // log2e/sqrt(8)
    u64 qq[4][8];
#pragma unroll
    for (int qi = 0; qi < 4; qi++) {
        const float* p = &g_q[(base + tid + qi * 128) * 64 + h * DH];
#pragma unroll
        for (int d = 0; d < 8; d++) {
            float a = p[d] * scale;
            qq[qi][d] = f2pack(a, a);
        }
    }

    u64 sum[4] = {0ULL, 0ULL, 0ULL, 0ULL};
    u64 acc[4][4] = {};

#pragma unroll 1
    for (int k0 = 0; k0 < NPG; k0 += 4) {
        u64 sA[4] = {0ULL, 0ULL, 0ULL, 0ULL};
        u64 sB[4] = {0ULL, 0ULL, 0ULL, 0ULL};
#pragma unroll
        for (int d = 0; d < 8; d++) {
            float4 kv = *(const float4*)&sK[d][k0];
            u64 k01 = f2pack(kv.x, kv.y);
            u64 k23 = f2pack(kv.z, kv.w);
#pragma unroll
            for (int qi = 0; qi < 4; qi++) {
                sA[qi] = fma2(qq[qi][d], k01, sA[qi]);
                sB[qi] = fma2(qq[qi][d], k23, sB[qi]);
            }
        }
        float p[4][4];
#pragma unroll
        for (int qi = 0; qi < 4; qi++) {
            float s0, s1;
            f2unpack(sA[qi], s0, s1); p[qi][0] = ex2(s0); p[qi][1] = ex2(s1);
            f2unpack(sB[qi], s0, s1); p[qi][2] = ex2(s0); p[qi][3] = ex2(s1);
            sum[qi] = add2(sum[qi], f2pack(p[qi][0], p[qi][1]));
            sum[qi] = add2(sum[qi], f2pack(p[qi][2], p[qi][3]));
        }
#pragma unroll
        for (int j = 0; j < 4; j++) {
            float4 vlo = sV4[k0 + j][0];
            float4 vhi = sV4[k0 + j][1];
            u64 v0 = f2pack(vlo.x, vlo.y);
            u64 v1 = f2pack(vlo.z, vlo.w);
            u64 v2 = f2pack(vhi.x, vhi.y);
            u64 v3 = f2pack(vhi.z, vhi.w);
#pragma unroll
            for (int qi = 0; qi < 4; qi++) {
                u64 pp = f2pack(p[qi][j], p[qi][j]);
                acc[qi][0] = fma2(pp, v0, acc[qi][0]);
                acc[qi][1] = fma2(pp, v1, acc[qi][1]);
                acc[qi][2] = fma2(pp, v2, acc[qi][2]);
                acc[qi][3] = fma2(pp, v3, acc[qi][3]);
            }
        }
    }
#pragma unroll
    for (int qi = 0; qi < 4; qi++) {
        float sl, sh; f2unpack(sum[qi], sl, sh);
        float inv = 1.0f / (sl + sh);
        float o[8];
#pragma unroll
        for (int pp = 0; pp < 4; pp++) f2unpack(acc[qi][pp], o[2 * pp], o[2 * pp + 1]);
        float* op = &g_ao[(base + tid + qi * 128) * 64 + h * DH];
        *(float4*)&op[0] = make_float4(o[0] * inv, o[1] * inv, o[2] * inv, o[3] * inv);
        *(float4*)&op[4] = make_float4(o[4] * inv, o[5] * inv, o[6] * inv, o[7] * inv);
    }
}

// ---------------- K7: out = LN(x1 + relu(ao @ wo + bo)) --------------------
__global__ void k7_out(const float* __restrict__ wo, const float* __restrict__ bo,
                       const float* __restrict__ g2, const float* __restrict__ b2,
                       float* __restrict__ out) {
    __shared__ float sw[4096];
    __shared__ float sx[16][64];
    int t = threadIdx.x;
    for (int i = t; i < 4096; i += 256) sw[i] = wo[i];
    int row0 = blockIdx.x * 16;
    for (int i = t; i < 1024; i += 256) sx[i >> 6][i & 63] = g_ao[row0 * 64 + i];
    __syncthreads();
    int r = t >> 4, j4 = t & 15;
    const float4* sw4 = (const float4*)sw;
    float4 a = make_float4(0.f, 0.f, 0.f, 0.f);
#pragma unroll
    for (int kk = 0; kk < 64; kk++) {
        float xv = sx[r][kk];
        float4 wv = sw4[kk * 16 + j4];
        a.x = fmaf(xv, wv.x, a.x);
        a.y = fmaf(xv, wv.y, a.y);
        a.z = fmaf(xv, wv.z, a.z);
        a.w = fmaf(xv, wv.w, a.w);
    }
    float4 bv = *(const float4*)&bo[j4 * 4];
    a.x = fmaxf(a.x + bv.x, 0.0f);
    a.y = fmaxf(a.y + bv.y, 0.0f);
    a.z = fmaxf(a.z + bv.z, 0.0f);
    a.w = fmaxf(a.w + bv.w, 0.0f);
    float4 x1v = *(const float4*)&g_x1[(row0 + r) * 64 + j4 * 4];
    float4 val = make_float4(x1v.x + a.x, x1v.y + a.y, x1v.z + a.z, x1v.w + a.w);
    float vsum = val.x + val.y + val.z + val.w;
    float vsq  = val.x * val.x + val.y * val.y + val.z * val.z + val.w * val.w;
#pragma unroll
    for (int o = 1; o < 16; o <<= 1) {
        vsum += __shfl_xor_sync(0xffffffffu, vsum, o);
        vsq  += __shfl_xor_sync(0xffffffffu, vsq, o);
    }
    float mu = vsum * (1.0f / 64.0f);
    float var = vsq * (1.0f / 64.0f) - mu * mu;
    float rstd = rsqrtf(var + 1e-5f);
    float4 gv = *(const float4*)&g2[j4 * 4];
    float4 bb = *(const float4*)&b2[j4 * 4];
    float4 ov;
    ov.x = (val.x - mu) * rstd * gv.x + bb.x;
    ov.y = (val.y - mu) * rstd * gv.y + bb.y;
    ov.z = (val.z - mu) * rstd * gv.z + bb.z;
    ov.w = (val.w - mu) * rstd * gv.w + bb.w;
    *(float4*)&out[(row0 + r) * 64 + j4 * 4] = ov;
}

// ---------------- launch ----------------------------------------------------
extern "C" void kernel_launch(void* const* d_in, const int* in_sizes, int n_in,
                              void* d_out, int out_size) {
    const float* x       = (const float*)d_in[0];
    const float* w_gat   = (const float*)d_in[1];
    const float* att_src = (const float*)d_in[2];
    const float* att_dst = (const float*)d_in[3];
    const float* b_gat   = (const float*)d_in[4];
    const float* g1      = (const float*)d_in[5];
    const float* b1      = (const float*)d_in[6];
    const float* wq      = (const float*)d_in[7];
    const float* bq      = (const float*)d_in[8];
    const float* wk      = (const float*)d_in[9];
    const float* bk      = (const float*)d_in[10];
    const float* wv      = (const float*)d_in[11];
    const float* bv      = (const float*)d_in[12];
    const float* wo      = (const float*)d_in[13];
    const float* bo      = (const float*)d_in[14];
    const float* g2      = (const float*)d_in[15];
    const float* b2      = (const float*)d_in[16];
    const int*   ei      = (const int*)d_in[17];
    float* out = (float*)d_out;

    static cudaStream_t s2 = nullptr;
    static cudaEvent_t evFork = nullptr, evJoin = nullptr;
    static void* cnt_addr = nullptr;
    if (s2 == nullptr) {
        cudaStreamCreateWithFlags(&s2, cudaStreamNonBlocking);
        cudaEventCreateWithFlags(&evFork, cudaEventDisableTiming);
        cudaEventCreateWithFlags(&evJoin, cudaEventDisableTiming);
        cudaGetSymbolAddress(&cnt_addr, g_cnt);
    }

    // fork: k1 (depends only on inputs) runs concurrently with CSR build
    cudaEventRecord(evFork, 0);
    cudaStreamWaitEvent(s2, evFork, 0);
    k1_gat_proj<<<N_NODES / 16, 256, 0, s2>>>(x, w_gat, att_src, att_dst);
    cudaEventRecord(evJoin, s2);

    cudaMemsetAsync(cnt_addr, 0, N_NODES * sizeof(int), 0);
    kc_scatter_pad<<<E_EDGES / 2 / 256, 256>>>(ei);

    // join: k5 needs both k1 outputs and CSR
    cudaStreamWaitEvent(0, evJoin, 0);
    k5_gat_agg<<<N_NODES * 32 / 256, 256>>>(x, b_gat, g1, b1);
    k_qkv<<<N_NODES / 64, 512>>>(wq, bq, wk, bk, wv, bv);
    k6_attn<<<B * HEADS, 128>>>();
    k7_out<<<N_NODES / 16, 256>>>(wo, bo, g2, b2, out);
}